// round 11
// baseline (speedup 1.0000x reference)
#include <cuda_runtime.h>
#include <cuda_bf16.h>
#include <cstdint>

// Problem dims
#define NSEQ 4096
#define DIM  1024

// GEMM tiling (R7 config): CTA 128x128x32, 8 warps (2x4) of 64x32, 2 CTAs/SM
#define BM 128
#define BN 128
#define BK 32
#define STG 3
#define ROW_PITCH 144                        // 36 floats: conflict-free for ldmatrix
#define B_OFF (BM * ROW_PITCH)               // 18432
#define STAGE_BYTES ((BM + BN) * ROW_PITCH)  // 36864
#define DYN_SMEM_BYTES (STG * STAGE_BYTES)   // 110592 -> 2 CTAs/SM

// ---------------- scratch (static device allocations; no cudaMalloc) ----------------
__device__ float g_xt[NSEQ * DIM];             // x rounded to tf32
__device__ float g_wt[3 * DIM * DIM];          // wq,wk,wv rounded, stacked [3072,1024]
__device__ float g_qkv[NSEQ * 3 * DIM];        // packed [4096, 3072]: Q|K|V
__device__ float g_vt[DIM * NSEQ];             // V^T [1024, 4096]
__device__ float g_S[(size_t)NSEQ * NSEQ];     // expS = tf32(exp(S/32))
__device__ float g_part[(size_t)NSEQ * 128];   // per-(xCTA,wn) row partial sums
__device__ float g_rowsum[NSEQ];               // softmax denominators

// ---------------- helpers ----------------
__device__ __forceinline__ float to_tf32(float x) {
    uint32_t u;
    asm volatile("cvt.rna.tf32.f32 %0, %1;" : "=r"(u) : "f"(x));
    return __uint_as_float(u);
}

__device__ __forceinline__ uint32_t smem_u32(const void* p) {
    return (uint32_t)__cvta_generic_to_shared(p);
}

__device__ __forceinline__ uint64_t gmem_u64(const void* p) {
    uint64_t g;
    asm volatile("cvta.to.global.u64 %0, %1;" : "=l"(g) : "l"(p));
    return g;
}

__device__ __forceinline__ void ldsm_x4(uint32_t& r0, uint32_t& r1, uint32_t& r2, uint32_t& r3,
                                        uint32_t addr) {
    asm volatile("ldmatrix.sync.aligned.m8n8.x4.shared.b16 {%0,%1,%2,%3}, [%4];\n"
                 : "=r"(r0), "=r"(r1), "=r"(r2), "=r"(r3)
                 : "r"(addr));
}

__device__ __forceinline__ void mma_tf32(float c[4], uint32_t a0, uint32_t a1, uint32_t a2,
                                         uint32_t a3, uint32_t b0, uint32_t b1) {
    asm volatile(
        "mma.sync.aligned.m16n8k8.row.col.f32.tf32.tf32.f32 "
        "{%0,%1,%2,%3}, {%4,%5,%6,%7}, {%8,%9}, {%0,%1,%2,%3};\n"
        : "+f"(c[0]), "+f"(c[1]), "+f"(c[2]), "+f"(c[3])
        : "r"(a0), "r"(a1), "r"(a2), "r"(a3), "r"(b0), "r"(b1));
}

#define CP_ASYNC16(dst, src) \
    asm volatile("cp.async.cg.shared.global [%0], [%1], 16;" :: "r"(dst), "l"(src))
#define CP_COMMIT() asm volatile("cp.async.commit_group;" ::: "memory")

// ---------------- convert inputs: fp32 -> tf32-rounded fp32 ----------------
__global__ void convert_kernel(const float* __restrict__ x, const float* __restrict__ wq,
                               const float* __restrict__ wk, const float* __restrict__ wv) {
    const int stride = gridDim.x * blockDim.x;
    const int tid = blockIdx.x * blockDim.x + threadIdx.x;
    const int nx4 = (NSEQ * DIM) / 4;
    for (int i = tid; i < nx4; i += stride) {
        float4 f = ((const float4*)x)[i];
        ((float4*)g_xt)[i] = make_float4(to_tf32(f.x), to_tf32(f.y), to_tf32(f.z), to_tf32(f.w));
    }
    const int nw4 = (DIM * DIM) / 4;
    for (int i = tid; i < nw4; i += stride) {
        float4 a = ((const float4*)wq)[i];
        float4 b = ((const float4*)wk)[i];
        float4 c = ((const float4*)wv)[i];
        ((float4*)g_wt)[i]           = make_float4(to_tf32(a.x), to_tf32(a.y), to_tf32(a.z), to_tf32(a.w));
        ((float4*)g_wt)[nw4 + i]     = make_float4(to_tf32(b.x), to_tf32(b.y), to_tf32(b.z), to_tf32(b.w));
        ((float4*)g_wt)[2 * nw4 + i] = make_float4(to_tf32(c.x), to_tf32(c.y), to_tf32(c.z), to_tf32(c.w));
    }
}

// ======== tf32 mma.sync GEMM (R7 core) + fused epilogues ============================
// C[M,N] = A[M,K] * B[N,K]^T ; row strides ldA/ldB/ldC.
// round_out: tf32-round outputs
// exp_part : C = tf32(exp(acc/32)); row partial sums -> part[row*128 + bx*4 + wn]
// divrow   : if non-null, outputs scaled by 1/divrow[row]
__global__ __launch_bounds__(256, 2)
void gemm_tt(const float* __restrict__ A, int ldA, const float* __restrict__ B, int ldB,
             float* __restrict__ C, int ldC, int K,
             int round_out, int exp_part,
             const float* __restrict__ divrow, float* __restrict__ part) {
    extern __shared__ char dynsm[];
    const uint32_t sm_base = smem_u32(dynsm);

    const int tid  = threadIdx.x;
    const int lane = tid & 31;
    const int warp = tid >> 5;
    const int wm = warp >> 2;   // 0..1 -> m offset wm*64
    const int wn = warp & 3;    // 0..3 -> n offset wn*32

    const int rm0 = blockIdx.y * BM;
    const int cn0 = blockIdx.x * BN;
    const int nchunks = K / BK;

    // per-thread load geometry: row r0 = tid>>3 (+32 per t), 16B col q
    const int r0 = tid >> 3;
    const int q  = tid & 7;
    uint64_t pA = gmem_u64(A) + ((size_t)(rm0 + r0) * ldA + q * 4) * 4;
    uint64_t pB = gmem_u64(B) + ((size_t)(cn0 + r0) * ldB + q * 4) * 4;
    const uint64_t stA = (uint64_t)ldA * 32 * 4;   // +32 rows
    const uint64_t stB = (uint64_t)ldB * 32 * 4;
    const uint32_t sOffA = r0 * ROW_PITCH + q * 16;
    const uint32_t sOffB = B_OFF + sOffA;

    float c[4][4][4];
#pragma unroll
    for (int i = 0; i < 4; i++)
#pragma unroll
        for (int j = 0; j < 4; j++)
#pragma unroll
            for (int r = 0; r < 4; r++) c[i][j][r] = 0.f;

    auto fill = [&](int stg) {
        const uint32_t s0 = sm_base + stg * STAGE_BYTES;
#pragma unroll
        for (int t = 0; t < 4; t++)
            CP_ASYNC16(s0 + sOffA + t * (32 * ROW_PITCH), pA + t * stA);
#pragma unroll
        for (int t = 0; t < 4; t++)
            CP_ASYNC16(s0 + sOffB + t * (32 * ROW_PITCH), pB + t * stB);
        pA += BK * 4;
        pB += BK * 4;
    };

    // prologue
    fill(0); CP_COMMIT();
    fill(1); CP_COMMIT();

    for (int i = 0; i < nchunks; i++) {
        const int s = i % STG;
        if (i + 2 < nchunks) {
            asm volatile("cp.async.wait_group 1;" ::: "memory");
        } else {
            asm volatile("cp.async.wait_group 0;" ::: "memory");
        }
        __syncthreads();

        if (i + 2 < nchunks) {
            fill((i + 2) % STG);
            CP_COMMIT();
        }

        const uint32_t sA = sm_base + s * STAGE_BYTES;
        const uint32_t sB = sA + B_OFF;
#pragma unroll
        for (int kk = 0; kk < BK; kk += 8) {
            uint32_t a[4][4], b[4][2];
#pragma unroll
            for (int i2 = 0; i2 < 4; i2++) {
                uint32_t addr = sA + (wm * 64 + i2 * 16 + (lane & 15)) * ROW_PITCH +
                                (kk + ((lane >> 4) << 2)) * 4;
                ldsm_x4(a[i2][0], a[i2][1], a[i2][2], a[i2][3], addr);
            }
#pragma unroll
            for (int j0 = 0; j0 < 4; j0 += 2) {
                int pair = lane >> 3;
                uint32_t addr = sB + (wn * 32 + (j0 + (pair >> 1)) * 8 + (lane & 7)) * ROW_PITCH +
                                (kk + ((pair & 1) << 2)) * 4;
                uint32_t r0_, r1_, r2_, r3_;
                ldsm_x4(r0_, r1_, r2_, r3_, addr);
                b[j0][0] = r0_; b[j0][1] = r1_; b[j0 + 1][0] = r2_; b[j0 + 1][1] = r3_;
            }
#pragma unroll
            for (int i2 = 0; i2 < 4; i2++)
#pragma unroll
                for (int j = 0; j < 4; j++)
                    mma_tf32(c[i2][j], a[i2][0], a[i2][1], a[i2][2], a[i2][3], b[j][0], b[j][1]);
        }
    }

    // epilogue
    const int tr = lane >> 2;
    const int tc = (lane & 3) * 2;
    const float scale = 0.03125f;   // 1/sqrt(1024)
#pragma unroll
    for (int i = 0; i < 4; i++) {
        const size_t row = (size_t)(rm0 + wm * 64 + i * 16 + tr);
        float d0 = 1.f, d1 = 1.f;
        if (divrow) {
            d0 = 1.f / divrow[row];
            d1 = 1.f / divrow[row + 8];
        }
        float s0 = 0.f, s1 = 0.f;
#pragma unroll
        for (int j = 0; j < 4; j++) {
            int col = cn0 + wn * 32 + j * 8 + tc;
            float v0 = c[i][j][0], v1 = c[i][j][1], v2 = c[i][j][2], v3 = c[i][j][3];
            if (exp_part) {
                v0 = to_tf32(__expf(v0 * scale));
                v1 = to_tf32(__expf(v1 * scale));
                v2 = to_tf32(__expf(v2 * scale));
                v3 = to_tf32(__expf(v3 * scale));
                s0 += v0 + v1;
                s1 += v2 + v3;
            } else if (round_out) {
                v0 = to_tf32(v0); v1 = to_tf32(v1); v2 = to_tf32(v2); v3 = to_tf32(v3);
            }
            if (divrow) { v0 *= d0; v1 *= d0; v2 *= d1; v3 *= d1; }
            *(float2*)&C[row * ldC + col]       = make_float2(v0, v1);
            *(float2*)&C[(row + 8) * ldC + col] = make_float2(v2, v3);
        }
        if (exp_part) {
            // quad-reduce across the 4 lanes sharing this row
            s0 += __shfl_xor_sync(0xffffffffu, s0, 1);
            s0 += __shfl_xor_sync(0xffffffffu, s0, 2);
            s1 += __shfl_xor_sync(0xffffffffu, s1, 1);
            s1 += __shfl_xor_sync(0xffffffffu, s1, 2);
            if ((lane & 3) == 0) {
                part[row * 128 + blockIdx.x * 4 + wn]       = s0;
                part[(row + 8) * 128 + blockIdx.x * 4 + wn] = s1;
            }
        }
    }
}

// ---------------- rowsum: warp per row, 4 loads + shfl reduce ----------------
__global__ void rowsum_kernel(const float* __restrict__ part, float* __restrict__ rs) {
    const int warp = (blockIdx.x * blockDim.x + threadIdx.x) >> 5;
    const int lane = threadIdx.x & 31;
    if (warp >= NSEQ) return;
    const float4 v = ((const float4*)(part + (size_t)warp * 128))[lane];
    float s = v.x + v.y + v.z + v.w;
#pragma unroll
    for (int o = 16; o; o >>= 1) s += __shfl_xor_sync(0xffffffffu, s, o);
    if (lane == 0) rs[warp] = s;
}

// ---------------- transpose: Vt[c][r] = QKV[r][2048 + c] ----------------
__global__ void transpose_v_kernel(const float* __restrict__ qkv, float* __restrict__ out) {
    __shared__ float tile[32][33];
    int cbase = blockIdx.x * 32;   // headdim index
    int rbase = blockIdx.y * 32;   // seq index
    int tx = threadIdx.x, ty = threadIdx.y;
#pragma unroll
    for (int j = 0; j < 32; j += 8)
        tile[ty + j][tx] = qkv[(size_t)(rbase + ty + j) * (3 * DIM) + 2 * DIM + cbase + tx];
    __syncthreads();
#pragma unroll
    for (int j = 0; j < 32; j += 8)
        out[(size_t)(cbase + ty + j) * NSEQ + rbase + tx] = tile[tx][ty + j];
}

// ---------------- launch ----------------
extern "C" void kernel_launch(void* const* d_in, const int* in_sizes, int n_in,
                              void* d_out, int out_size) {
    const float* x  = (const float*)d_in[0];
    const float* wq = (const float*)d_in[1];
    const float* wk = (const float*)d_in[2];
    const float* wv = (const float*)d_in[3];
    float* out = (float*)d_out;

    float *p_xt, *p_wt, *p_qkv, *p_vt, *p_S, *p_part, *p_rs;
    cudaGetSymbolAddress((void**)&p_xt, g_xt);
    cudaGetSymbolAddress((void**)&p_wt, g_wt);
    cudaGetSymbolAddress((void**)&p_qkv, g_qkv);
    cudaGetSymbolAddress((void**)&p_vt, g_vt);
    cudaGetSymbolAddress((void**)&p_S, g_S);
    cudaGetSymbolAddress((void**)&p_part, g_part);
    cudaGetSymbolAddress((void**)&p_rs, g_rowsum);

    cudaFuncSetAttribute(gemm_tt, cudaFuncAttributeMaxDynamicSharedMemorySize, DYN_SMEM_BYTES);

    // 1) round inputs to tf32 (clean GEMM mainloops)
    convert_kernel<<<2048, 256>>>(x, wq, wk, wv);

    // 2) QKV = xt @ Wt^T (stacked weights), packed [4096, 3072], tf32-rounded out
    gemm_tt<<<dim3(3 * DIM / BN, NSEQ / BM), 256, DYN_SMEM_BYTES>>>(
        p_xt, DIM, p_wt, DIM, p_qkv, 3 * DIM, DIM, 1, 0, nullptr, nullptr);

    // 3) V^T
    transpose_v_kernel<<<dim3(DIM / 32, NSEQ / 32), dim3(32, 8)>>>(p_qkv, p_vt);

    // 4) expS = tf32(exp((Q @ K^T)/32)) + row partial sums (fused softmax numerator)
    gemm_tt<<<dim3(NSEQ / BN, NSEQ / BM), 256, DYN_SMEM_BYTES>>>(
        p_qkv, 3 * DIM, p_qkv + DIM, 3 * DIM, p_S, NSEQ, DIM, 0, 1, nullptr, p_part);

    // 5) rowsum (warp per row)
    rowsum_kernel<<<NSEQ * 32 / 256, 256>>>(p_part, p_rs);

    // 6) out = (expS @ V) / rowsum  (fused softmax denominator)
    gemm_tt<<<dim3(DIM / BN, NSEQ / BM), 256, DYN_SMEM_BYTES>>>(
        p_S, NSEQ, p_vt, NSEQ, out, DIM, NSEQ, 0, 0, p_rs, nullptr);
}

// round 15
// speedup vs baseline: 1.5509x; 1.5509x over previous
#include <cuda_runtime.h>
#include <cuda_bf16.h>
#include <cstdint>

// Problem dims
#define NSEQ 4096
#define DIM  1024

// GEMM tiling (R7 config): CTA 128x128x32, 8 warps (2x4) of 64x32, 2 CTAs/SM
#define BM 128
#define BN 128
#define BK 32
#define STG 3
#define ROW_PITCH 144                        // 36 floats: conflict-free for ldmatrix
#define B_OFF (BM * ROW_PITCH)               // 18432
#define STAGE_BYTES ((BM + BN) * ROW_PITCH)  // 36864
#define DYN_SMEM_BYTES (STG * STAGE_BYTES)   // 110592 -> 2 CTAs/SM

// ---------------- scratch (static device allocations; no cudaMalloc) ----------------
__device__ float g_xt[NSEQ * DIM];             // x rounded to tf32
__device__ float g_wt[3 * DIM * DIM];          // wq,wk,wv rounded, stacked [3072,1024]
__device__ float g_qkv[NSEQ * 3 * DIM];        // packed [4096, 3072]: Q|K|V
__device__ float g_vt[DIM * NSEQ];             // V^T [1024, 4096]
__device__ float g_S[(size_t)NSEQ * NSEQ];     // expS = tf32(exp(S/32))
__device__ float g_part[(size_t)NSEQ * 128];   // per-(xCTA,wn) row partial sums
__device__ float g_rowsum[NSEQ];               // softmax denominators

// ---------------- helpers ----------------
__device__ __forceinline__ float to_tf32(float x) {
    uint32_t u;
    asm volatile("cvt.rna.tf32.f32 %0, %1;" : "=r"(u) : "f"(x));
    return __uint_as_float(u);
}

__device__ __forceinline__ uint32_t smem_u32(const void* p) {
    return (uint32_t)__cvta_generic_to_shared(p);
}

__device__ __forceinline__ uint64_t gmem_u64(const void* p) {
    uint64_t g;
    asm volatile("cvta.to.global.u64 %0, %1;" : "=l"(g) : "l"(p));
    return g;
}

__device__ __forceinline__ void ldsm_x4(uint32_t& r0, uint32_t& r1, uint32_t& r2, uint32_t& r3,
                                        uint32_t addr) {
    asm volatile("ldmatrix.sync.aligned.m8n8.x4.shared.b16 {%0,%1,%2,%3}, [%4];\n"
                 : "=r"(r0), "=r"(r1), "=r"(r2), "=r"(r3)
                 : "r"(addr));
}

__device__ __forceinline__ void mma_tf32(float c[4], uint32_t a0, uint32_t a1, uint32_t a2,
                                         uint32_t a3, uint32_t b0, uint32_t b1) {
    asm volatile(
        "mma.sync.aligned.m16n8k8.row.col.f32.tf32.tf32.f32 "
        "{%0,%1,%2,%3}, {%4,%5,%6,%7}, {%8,%9}, {%0,%1,%2,%3};\n"
        : "+f"(c[0]), "+f"(c[1]), "+f"(c[2]), "+f"(c[3])
        : "r"(a0), "r"(a1), "r"(a2), "r"(a3), "r"(b0), "r"(b1));
}

#define CP_ASYNC16(dst, src) \
    asm volatile("cp.async.cg.shared.global [%0], [%1], 16;" :: "r"(dst), "l"(src))
#define CP_COMMIT() asm volatile("cp.async.commit_group;" ::: "memory")

// ---------------- convert inputs: fp32 -> tf32-rounded fp32 ----------------
__global__ void convert_kernel(const float* __restrict__ x, const float* __restrict__ wq,
                               const float* __restrict__ wk, const float* __restrict__ wv) {
    const int stride = gridDim.x * blockDim.x;
    const int tid = blockIdx.x * blockDim.x + threadIdx.x;
    const int nx4 = (NSEQ * DIM) / 4;
    for (int i = tid; i < nx4; i += stride) {
        float4 f = ((const float4*)x)[i];
        ((float4*)g_xt)[i] = make_float4(to_tf32(f.x), to_tf32(f.y), to_tf32(f.z), to_tf32(f.w));
    }
    const int nw4 = (DIM * DIM) / 4;
    for (int i = tid; i < nw4; i += stride) {
        float4 a = ((const float4*)wq)[i];
        float4 b = ((const float4*)wk)[i];
        float4 c = ((const float4*)wv)[i];
        ((float4*)g_wt)[i]           = make_float4(to_tf32(a.x), to_tf32(a.y), to_tf32(a.z), to_tf32(a.w));
        ((float4*)g_wt)[nw4 + i]     = make_float4(to_tf32(b.x), to_tf32(b.y), to_tf32(b.z), to_tf32(b.w));
        ((float4*)g_wt)[2 * nw4 + i] = make_float4(to_tf32(c.x), to_tf32(c.y), to_tf32(c.z), to_tf32(c.w));
    }
}

// ======== tf32 mma.sync GEMM (R7 core) + fused epilogues ============================
// C[M,N] = A[M,K] * B[N,K]^T ; row strides ldA/ldB/ldC.
// round_out: tf32-round outputs
// exp_part : C = tf32(exp(acc/32)); row partial sums -> part[row*128 + bx*4 + wn]
// divrow   : if non-null, outputs scaled by 1/divrow[row]
__global__ __launch_bounds__(256, 2)
void gemm_tt(const float* __restrict__ A, int ldA, const float* __restrict__ B, int ldB,
             float* __restrict__ C, int ldC, int K,
             int round_out, int exp_part,
             const float* __restrict__ divrow, float* __restrict__ part) {
    extern __shared__ char dynsm[];
    const uint32_t sm_base = smem_u32(dynsm);

    const int tid  = threadIdx.x;
    const int lane = tid & 31;
    const int warp = tid >> 5;
    const int wm = warp >> 2;   // 0..1 -> m offset wm*64
    const int wn = warp & 3;    // 0..3 -> n offset wn*32

    const int rm0 = blockIdx.y * BM;
    const int cn0 = blockIdx.x * BN;
    const int nchunks = K / BK;

    // per-thread load geometry: row r0 = tid>>3 (+32 per t), 16B col q
    const int r0 = tid >> 3;
    const int q  = tid & 7;
    uint64_t pA = gmem_u64(A) + ((size_t)(rm0 + r0) * ldA + q * 4) * 4;
    uint64_t pB = gmem_u64(B) + ((size_t)(cn0 + r0) * ldB + q * 4) * 4;
    const uint64_t stA = (uint64_t)ldA * 32 * 4;   // +32 rows
    const uint64_t stB = (uint64_t)ldB * 32 * 4;
    const uint32_t sOffA = r0 * ROW_PITCH + q * 16;
    const uint32_t sOffB = B_OFF + sOffA;

    float c[4][4][4];
#pragma unroll
    for (int i = 0; i < 4; i++)
#pragma unroll
        for (int j = 0; j < 4; j++)
#pragma unroll
            for (int r = 0; r < 4; r++) c[i][j][r] = 0.f;

    auto fill = [&](int stg) {
        const uint32_t s0 = sm_base + stg * STAGE_BYTES;
#pragma unroll
        for (int t = 0; t < 4; t++)
            CP_ASYNC16(s0 + sOffA + t * (32 * ROW_PITCH), pA + t * stA);
#pragma unroll
        for (int t = 0; t < 4; t++)
            CP_ASYNC16(s0 + sOffB + t * (32 * ROW_PITCH), pB + t * stB);
        pA += BK * 4;
        pB += BK * 4;
    };

    // prologue
    fill(0); CP_COMMIT();
    fill(1); CP_COMMIT();

    for (int i = 0; i < nchunks; i++) {
        const int s = i % STG;
        if (i + 2 < nchunks) {
            asm volatile("cp.async.wait_group 1;" ::: "memory");
        } else {
            asm volatile("cp.async.wait_group 0;" ::: "memory");
        }
        __syncthreads();

        if (i + 2 < nchunks) {
            fill((i + 2) % STG);
            CP_COMMIT();
        }

        const uint32_t sA = sm_base + s * STAGE_BYTES;
        const uint32_t sB = sA + B_OFF;
#pragma unroll
        for (int kk = 0; kk < BK; kk += 8) {
            uint32_t a[4][4], b[4][2];
#pragma unroll
            for (int i2 = 0; i2 < 4; i2++) {
                uint32_t addr = sA + (wm * 64 + i2 * 16 + (lane & 15)) * ROW_PITCH +
                                (kk + ((lane >> 4) << 2)) * 4;
                ldsm_x4(a[i2][0], a[i2][1], a[i2][2], a[i2][3], addr);
            }
#pragma unroll
            for (int j0 = 0; j0 < 4; j0 += 2) {
                int pair = lane >> 3;
                uint32_t addr = sB + (wn * 32 + (j0 + (pair >> 1)) * 8 + (lane & 7)) * ROW_PITCH +
                                (kk + ((pair & 1) << 2)) * 4;
                uint32_t r0_, r1_, r2_, r3_;
                ldsm_x4(r0_, r1_, r2_, r3_, addr);
                b[j0][0] = r0_; b[j0][1] = r1_; b[j0 + 1][0] = r2_; b[j0 + 1][1] = r3_;
            }
#pragma unroll
            for (int i2 = 0; i2 < 4; i2++)
#pragma unroll
                for (int j = 0; j < 4; j++)
                    mma_tf32(c[i2][j], a[i2][0], a[i2][1], a[i2][2], a[i2][3], b[j][0], b[j][1]);
        }
    }

    // epilogue
    const int tr = lane >> 2;
    const int tc = (lane & 3) * 2;
    const float scale = 0.03125f;   // 1/sqrt(1024)
#pragma unroll
    for (int i = 0; i < 4; i++) {
        const size_t row = (size_t)(rm0 + wm * 64 + i * 16 + tr);
        float d0 = 1.f, d1 = 1.f;
        if (divrow) {
            d0 = __frcp_rn(divrow[row]);
            d1 = __frcp_rn(divrow[row + 8]);
        }
        float s0 = 0.f, s1 = 0.f;
#pragma unroll
        for (int j = 0; j < 4; j++) {
            int col = cn0 + wn * 32 + j * 8 + tc;
            float v0 = c[i][j][0], v1 = c[i][j][1], v2 = c[i][j][2], v3 = c[i][j][3];
            if (exp_part) {
                v0 = to_tf32(__expf(v0 * scale));
                v1 = to_tf32(__expf(v1 * scale));
                v2 = to_tf32(__expf(v2 * scale));
                v3 = to_tf32(__expf(v3 * scale));
                s0 += v0 + v1;
                s1 += v2 + v3;
            } else if (round_out) {
                v0 = to_tf32(v0); v1 = to_tf32(v1); v2 = to_tf32(v2); v3 = to_tf32(v3);
            }
            if (divrow) { v0 *= d0; v1 *= d0; v2 *= d1; v3 *= d1; }
            *(float2*)&C[row * ldC + col]       = make_float2(v0, v1);
            *(float2*)&C[(row + 8) * ldC + col] = make_float2(v2, v3);
        }
        if (exp_part) {
            // quad-reduce across the 4 lanes sharing this row
            s0 += __shfl_xor_sync(0xffffffffu, s0, 1);
            s0 += __shfl_xor_sync(0xffffffffu, s0, 2);
            s1 += __shfl_xor_sync(0xffffffffu, s1, 1);
            s1 += __shfl_xor_sync(0xffffffffu, s1, 2);
            if ((lane & 3) == 0) {
                part[row * 128 + blockIdx.x * 4 + wn]       = s0;
                part[(row + 8) * 128 + blockIdx.x * 4 + wn] = s1;
            }
        }
    }
}

// ---------------- rowsum: warp per row, 4 loads + shfl reduce ----------------
__global__ void rowsum_kernel(const float* __restrict__ part, float* __restrict__ rs) {
    const int warp = (blockIdx.x * blockDim.x + threadIdx.x) >> 5;
    const int lane = threadIdx.x & 31;
    if (warp >= NSEQ) return;
    const float4 v = ((const float4*)(part + (size_t)warp * 128))[lane];
    float s = v.x + v.y + v.z + v.w;
#pragma unroll
    for (int o = 16; o; o >>= 1) s += __shfl_xor_sync(0xffffffffu, s, o);
    if (lane == 0) rs[warp] = s;
}

// ---------------- transpose: Vt[c][r] = QKV[r][2048 + c] ----------------
__global__ void transpose_v_kernel(const float* __restrict__ qkv, float* __restrict__ out) {
    __shared__ float tile[32][33];
    int cbase = blockIdx.x * 32;   // headdim index
    int rbase = blockIdx.y * 32;   // seq index
    int tx = threadIdx.x, ty = threadIdx.y;
#pragma unroll
    for (int j = 0; j < 32; j += 8)
        tile[ty + j][tx] = qkv[(size_t)(rbase + ty + j) * (3 * DIM) + 2 * DIM + cbase + tx];
    __syncthreads();
#pragma unroll
    for (int j = 0; j < 32; j += 8)
        out[(size_t)(cbase + ty + j) * NSEQ + rbase + tx] = tile[tx][ty + j];
}

// ---------------- launch ----------------
extern "C" void kernel_launch(void* const* d_in, const int* in_sizes, int n_in,
                              void* d_out, int out_size) {
    const float* x  = (const float*)d_in[0];
    const float* wq = (const float*)d_in[1];
    const float* wk = (const float*)d_in[2];
    const float* wv = (const float*)d_in[3];
    float* out = (float*)d_out;

    float *p_xt, *p_wt, *p_qkv, *p_vt, *p_S, *p_part, *p_rs;
    cudaGetSymbolAddress((void**)&p_xt, g_xt);
    cudaGetSymbolAddress((void**)&p_wt, g_wt);
    cudaGetSymbolAddress((void**)&p_qkv, g_qkv);
    cudaGetSymbolAddress((void**)&p_vt, g_vt);
    cudaGetSymbolAddress((void**)&p_S, g_S);
    cudaGetSymbolAddress((void**)&p_part, g_part);
    cudaGetSymbolAddress((void**)&p_rs, g_rowsum);

    cudaFuncSetAttribute(gemm_tt, cudaFuncAttributeMaxDynamicSharedMemorySize, DYN_SMEM_BYTES);

    // 1) round inputs to tf32 (clean GEMM mainloops)
    convert_kernel<<<2048, 256>>>(x, wq, wk, wv);

    // 2) QKV = xt @ Wt^T (stacked weights), packed [4096, 3072], tf32-rounded out
    gemm_tt<<<dim3(3 * DIM / BN, NSEQ / BM), 256, DYN_SMEM_BYTES>>>(
        p_xt, DIM, p_wt, DIM, p_qkv, 3 * DIM, DIM, 1, 0, nullptr, nullptr);

    // 3) V^T
    transpose_v_kernel<<<dim3(DIM / 32, NSEQ / 32), dim3(32, 8)>>>(p_qkv, p_vt);

    // 4) expS = tf32(exp((Q @ K^T)/32)) + row partial sums (fused softmax numerator)
    gemm_tt<<<dim3(NSEQ / BN, NSEQ / BM), 256, DYN_SMEM_BYTES>>>(
        p_qkv, 3 * DIM, p_qkv + DIM, 3 * DIM, p_S, NSEQ, DIM, 0, 1, nullptr, p_part);

    // 5) rowsum (warp per row)
    rowsum_kernel<<<NSEQ * 32 / 256, 256>>>(p_part, p_rs);

    // 6) out = (expS @ V) / rowsum  (fused softmax denominator)
    gemm_tt<<<dim3(DIM / BN, NSEQ / BM), 256, DYN_SMEM_BYTES>>>(
        p_S, NSEQ, p_vt, NSEQ, out, DIM, NSEQ, 0, 0, p_rs, nullptr);
}

// round 16
// speedup vs baseline: 1.8746x; 1.2087x over previous
#include <cuda_runtime.h>
#include <cuda_fp16.h>
#include <cstdint>

// Problem dims
#define NSEQ 4096
#define DIM  1024

// GEMM tiling (R7 config): CTA 128x128x32(tf32)/64(fp16), 8 warps (2x4) of 64x32, 2 CTAs/SM
#define BM 128
#define BN 128
#define BK 32
#define STG 3
#define ROW_PITCH 144                        // 128B rows + 16B pad: conflict-free ldmatrix
#define B_OFF (BM * ROW_PITCH)               // 18432
#define STAGE_BYTES ((BM + BN) * ROW_PITCH)  // 36864
#define DYN_SMEM_BYTES (STG * STAGE_BYTES)   // 110592 -> 2 CTAs/SM

// ---------------- scratch (static device allocations; no cudaMalloc) ----------------
__device__ float  g_xt[NSEQ * DIM];             // x rounded to tf32
__device__ float  g_wt[3 * DIM * DIM];          // wq,wk,wv rounded, stacked [3072,1024]
__device__ float  g_qkv[NSEQ * 3 * DIM];        // packed [4096, 3072]: Q|K|V
__device__ __half g_vt[DIM * NSEQ];             // V^T [1024, 4096] fp16
__device__ __half g_S[(size_t)NSEQ * NSEQ];     // expS = fp16(exp(S/32))
__device__ float  g_part[(size_t)NSEQ * 128];   // per-(xCTA,wn) row partial sums
__device__ float  g_rowsum[NSEQ];               // softmax denominators

// ---------------- helpers ----------------
__device__ __forceinline__ float to_tf32(float x) {
    uint32_t u;
    asm volatile("cvt.rna.tf32.f32 %0, %1;" : "=r"(u) : "f"(x));
    return __uint_as_float(u);
}

__device__ __forceinline__ uint32_t smem_u32(const void* p) {
    return (uint32_t)__cvta_generic_to_shared(p);
}

__device__ __forceinline__ uint64_t gmem_u64(const void* p) {
    uint64_t g;
    asm volatile("cvta.to.global.u64 %0, %1;" : "=l"(g) : "l"(p));
    return g;
}

__device__ __forceinline__ void ldsm_x4(uint32_t& r0, uint32_t& r1, uint32_t& r2, uint32_t& r3,
                                        uint32_t addr) {
    asm volatile("ldmatrix.sync.aligned.m8n8.x4.shared.b16 {%0,%1,%2,%3}, [%4];\n"
                 : "=r"(r0), "=r"(r1), "=r"(r2), "=r"(r3)
                 : "r"(addr));
}

__device__ __forceinline__ void mma_tf32(float c[4], uint32_t a0, uint32_t a1, uint32_t a2,
                                         uint32_t a3, uint32_t b0, uint32_t b1) {
    asm volatile(
        "mma.sync.aligned.m16n8k8.row.col.f32.tf32.tf32.f32 "
        "{%0,%1,%2,%3}, {%4,%5,%6,%7}, {%8,%9}, {%0,%1,%2,%3};\n"
        : "+f"(c[0]), "+f"(c[1]), "+f"(c[2]), "+f"(c[3])
        : "r"(a0), "r"(a1), "r"(a2), "r"(a3), "r"(b0), "r"(b1));
}

__device__ __forceinline__ void mma_f16(float c[4], uint32_t a0, uint32_t a1, uint32_t a2,
                                        uint32_t a3, uint32_t b0, uint32_t b1) {
    asm volatile(
        "mma.sync.aligned.m16n8k16.row.col.f32.f16.f16.f32 "
        "{%0,%1,%2,%3}, {%4,%5,%6,%7}, {%8,%9}, {%0,%1,%2,%3};\n"
        : "+f"(c[0]), "+f"(c[1]), "+f"(c[2]), "+f"(c[3])
        : "r"(a0), "r"(a1), "r"(a2), "r"(a3), "r"(b0), "r"(b1));
}

#define CP_ASYNC16(dst, src) \
    asm volatile("cp.async.cg.shared.global [%0], [%1], 16;" :: "r"(dst), "l"(src))
#define CP_COMMIT() asm volatile("cp.async.commit_group;" ::: "memory")

// ---------------- convert inputs: fp32 -> tf32-rounded fp32 ----------------
__global__ void convert_kernel(const float* __restrict__ x, const float* __restrict__ wq,
                               const float* __restrict__ wk, const float* __restrict__ wv) {
    const int stride = gridDim.x * blockDim.x;
    const int tid = blockIdx.x * blockDim.x + threadIdx.x;
    const int nx4 = (NSEQ * DIM) / 4;
    for (int i = tid; i < nx4; i += stride) {
        float4 f = ((const float4*)x)[i];
        ((float4*)g_xt)[i] = make_float4(to_tf32(f.x), to_tf32(f.y), to_tf32(f.z), to_tf32(f.w));
    }
    const int nw4 = (DIM * DIM) / 4;
    for (int i = tid; i < nw4; i += stride) {
        float4 a = ((const float4*)wq)[i];
        float4 b = ((const float4*)wk)[i];
        float4 c = ((const float4*)wv)[i];
        ((float4*)g_wt)[i]           = make_float4(to_tf32(a.x), to_tf32(a.y), to_tf32(a.z), to_tf32(a.w));
        ((float4*)g_wt)[nw4 + i]     = make_float4(to_tf32(b.x), to_tf32(b.y), to_tf32(b.z), to_tf32(b.w));
        ((float4*)g_wt)[2 * nw4 + i] = make_float4(to_tf32(c.x), to_tf32(c.y), to_tf32(c.z), to_tf32(c.w));
    }
}

// ======== tf32 mma.sync GEMM (R7 core): QKV (round_out) and S (exp->fp16 + partials) ==
__global__ __launch_bounds__(256, 2)
void gemm_tt(const float* __restrict__ A, int ldA, const float* __restrict__ B, int ldB,
             float* __restrict__ C, __half* __restrict__ Ch, int ldC, int K,
             int round_out, int exp_part, float* __restrict__ part) {
    extern __shared__ char dynsm[];
    const uint32_t sm_base = smem_u32(dynsm);

    const int tid  = threadIdx.x;
    const int lane = tid & 31;
    const int warp = tid >> 5;
    const int wm = warp >> 2;
    const int wn = warp & 3;

    const int rm0 = blockIdx.y * BM;
    const int cn0 = blockIdx.x * BN;
    const int nchunks = K / BK;

    const int r0 = tid >> 3;
    const int q  = tid & 7;
    uint64_t pA = gmem_u64(A) + ((size_t)(rm0 + r0) * ldA + q * 4) * 4;
    uint64_t pB = gmem_u64(B) + ((size_t)(cn0 + r0) * ldB + q * 4) * 4;
    const uint64_t stA = (uint64_t)ldA * 32 * 4;
    const uint64_t stB = (uint64_t)ldB * 32 * 4;
    const uint32_t sOffA = r0 * ROW_PITCH + q * 16;
    const uint32_t sOffB = B_OFF + sOffA;

    float c[4][4][4];
#pragma unroll
    for (int i = 0; i < 4; i++)
#pragma unroll
        for (int j = 0; j < 4; j++)
#pragma unroll
            for (int r = 0; r < 4; r++) c[i][j][r] = 0.f;

    auto fill = [&](int stg) {
        const uint32_t s0 = sm_base + stg * STAGE_BYTES;
#pragma unroll
        for (int t = 0; t < 4; t++)
            CP_ASYNC16(s0 + sOffA + t * (32 * ROW_PITCH), pA + t * stA);
#pragma unroll
        for (int t = 0; t < 4; t++)
            CP_ASYNC16(s0 + sOffB + t * (32 * ROW_PITCH), pB + t * stB);
        pA += BK * 4;
        pB += BK * 4;
    };

    fill(0); CP_COMMIT();
    fill(1); CP_COMMIT();

    for (int i = 0; i < nchunks; i++) {
        const int s = i % STG;
        if (i + 2 < nchunks) {
            asm volatile("cp.async.wait_group 1;" ::: "memory");
        } else {
            asm volatile("cp.async.wait_group 0;" ::: "memory");
        }
        __syncthreads();

        if (i + 2 < nchunks) {
            fill((i + 2) % STG);
            CP_COMMIT();
        }

        const uint32_t sA = sm_base + s * STAGE_BYTES;
        const uint32_t sB = sA + B_OFF;
#pragma unroll
        for (int kk = 0; kk < BK; kk += 8) {
            uint32_t a[4][4], b[4][2];
#pragma unroll
            for (int i2 = 0; i2 < 4; i2++) {
                uint32_t addr = sA + (wm * 64 + i2 * 16 + (lane & 15)) * ROW_PITCH +
                                (kk + ((lane >> 4) << 2)) * 4;
                ldsm_x4(a[i2][0], a[i2][1], a[i2][2], a[i2][3], addr);
            }
#pragma unroll
            for (int j0 = 0; j0 < 4; j0 += 2) {
                int pair = lane >> 3;
                uint32_t addr = sB + (wn * 32 + (j0 + (pair >> 1)) * 8 + (lane & 7)) * ROW_PITCH +
                                (kk + ((pair & 1) << 2)) * 4;
                uint32_t r0_, r1_, r2_, r3_;
                ldsm_x4(r0_, r1_, r2_, r3_, addr);
                b[j0][0] = r0_; b[j0][1] = r1_; b[j0 + 1][0] = r2_; b[j0 + 1][1] = r3_;
            }
#pragma unroll
            for (int i2 = 0; i2 < 4; i2++)
#pragma unroll
                for (int j = 0; j < 4; j++)
                    mma_tf32(c[i2][j], a[i2][0], a[i2][1], a[i2][2], a[i2][3], b[j][0], b[j][1]);
        }
    }

    // epilogue
    const int tr = lane >> 2;
    const int tc = (lane & 3) * 2;
    const float scale = 0.03125f;   // 1/sqrt(1024)
#pragma unroll
    for (int i = 0; i < 4; i++) {
        const size_t row = (size_t)(rm0 + wm * 64 + i * 16 + tr);
        float s0 = 0.f, s1 = 0.f;
#pragma unroll
        for (int j = 0; j < 4; j++) {
            int col = cn0 + wn * 32 + j * 8 + tc;
            float v0 = c[i][j][0], v1 = c[i][j][1], v2 = c[i][j][2], v3 = c[i][j][3];
            if (exp_part) {
                // round to fp16 (what PV consumes), sum rounded values for denominator
                __half h0 = __float2half_rn(__expf(v0 * scale));
                __half h1 = __float2half_rn(__expf(v1 * scale));
                __half h2 = __float2half_rn(__expf(v2 * scale));
                __half h3 = __float2half_rn(__expf(v3 * scale));
                s0 += __half2float(h0) + __half2float(h1);
                s1 += __half2float(h2) + __half2float(h3);
                *(__half2*)&Ch[row * ldC + col]       = __halves2half2(h0, h1);
                *(__half2*)&Ch[(row + 8) * ldC + col] = __halves2half2(h2, h3);
            } else {
                if (round_out) { v0 = to_tf32(v0); v1 = to_tf32(v1); v2 = to_tf32(v2); v3 = to_tf32(v3); }
                *(float2*)&C[row * ldC + col]       = make_float2(v0, v1);
                *(float2*)&C[(row + 8) * ldC + col] = make_float2(v2, v3);
            }
        }
        if (exp_part) {
            s0 += __shfl_xor_sync(0xffffffffu, s0, 1);
            s0 += __shfl_xor_sync(0xffffffffu, s0, 2);
            s1 += __shfl_xor_sync(0xffffffffu, s1, 1);
            s1 += __shfl_xor_sync(0xffffffffu, s1, 2);
            if ((lane & 3) == 0) {
                part[row * 128 + blockIdx.x * 4 + wn]       = s0;
                part[(row + 8) * 128 + blockIdx.x * 4 + wn] = s1;
            }
        }
    }
}

// ======== fp16 mma.sync GEMM for PV: out[M,N] = (A_h[M,K] * B_h[N,K]^T) / rowsum =====
// BK=64 fp16 = 128B rows, same 144B pitch / stage sizes / pipeline as tf32 core.
#define HBK 64
__global__ __launch_bounds__(256, 2)
void gemm_pv(const __half* __restrict__ A, int ldA, const __half* __restrict__ B, int ldB,
             float* __restrict__ C, int ldC, int K, const float* __restrict__ divrow) {
    extern __shared__ char dynsm[];
    const uint32_t sm_base = smem_u32(dynsm);

    const int tid  = threadIdx.x;
    const int lane = tid & 31;
    const int warp = tid >> 5;
    const int wm = warp >> 2;
    const int wn = warp & 3;

    const int rm0 = blockIdx.y * BM;
    const int cn0 = blockIdx.x * BN;
    const int nchunks = K / HBK;

    const int r0 = tid >> 3;
    const int q  = tid & 7;
    uint64_t pA = gmem_u64(A) + ((size_t)(rm0 + r0) * ldA) * 2 + q * 16;
    uint64_t pB = gmem_u64(B) + ((size_t)(cn0 + r0) * ldB) * 2 + q * 16;
    const uint64_t stA = (uint64_t)ldA * 32 * 2;
    const uint64_t stB = (uint64_t)ldB * 32 * 2;
    const uint32_t sOffA = r0 * ROW_PITCH + q * 16;
    const uint32_t sOffB = B_OFF + sOffA;

    float c[4][4][4];
#pragma unroll
    for (int i = 0; i < 4; i++)
#pragma unroll
        for (int j = 0; j < 4; j++)
#pragma unroll
            for (int r = 0; r < 4; r++) c[i][j][r] = 0.f;

    auto fill = [&](int stg) {
        const uint32_t s0 = sm_base + stg * STAGE_BYTES;
#pragma unroll
        for (int t = 0; t < 4; t++)
            CP_ASYNC16(s0 + sOffA + t * (32 * ROW_PITCH), pA + t * stA);
#pragma unroll
        for (int t = 0; t < 4; t++)
            CP_ASYNC16(s0 + sOffB + t * (32 * ROW_PITCH), pB + t * stB);
        pA += HBK * 2;
        pB += HBK * 2;
    };

    fill(0); CP_COMMIT();
    fill(1); CP_COMMIT();

    for (int i = 0; i < nchunks; i++) {
        const int s = i % STG;
        if (i + 2 < nchunks) {
            asm volatile("cp.async.wait_group 1;" ::: "memory");
        } else {
            asm volatile("cp.async.wait_group 0;" ::: "memory");
        }
        __syncthreads();

        if (i + 2 < nchunks) {
            fill((i + 2) % STG);
            CP_COMMIT();
        }

        const uint32_t sA = sm_base + s * STAGE_BYTES;
        const uint32_t sB = sA + B_OFF;
#pragma unroll
        for (int kk = 0; kk < 4; kk++) {          // 4 x k16
            uint32_t a[4][4], b[4][2];
#pragma unroll
            for (int i2 = 0; i2 < 4; i2++) {
                // m16k16 A frag: lanes 0-7 rows 0-7 +0B, 8-15 rows 8-15 +0B,
                //                16-23 rows 0-7 +16B, 24-31 rows 8-15 +16B
                uint32_t addr = sA + (wm * 64 + i2 * 16 + (lane & 15)) * ROW_PITCH +
                                kk * 32 + ((lane >> 4) << 4);
                ldsm_x4(a[i2][0], a[i2][1], a[i2][2], a[i2][3], addr);
            }
#pragma unroll
            for (int j0 = 0; j0 < 4; j0 += 2) {
                // two n8k16 B frags: lanes 0-7 rows n0-7 +0, 8-15 n0-7 +16,
                //                    16-23 n8-15 +0, 24-31 n8-15 +16
                uint32_t addr = sB + (wn * 32 + (j0 + ((lane >> 4) & 1)) * 8 + (lane & 7)) * ROW_PITCH +
                                kk * 32 + (((lane >> 3) & 1) << 4);
                uint32_t r0_, r1_, r2_, r3_;
                ldsm_x4(r0_, r1_, r2_, r3_, addr);
                b[j0][0] = r0_; b[j0][1] = r1_; b[j0 + 1][0] = r2_; b[j0 + 1][1] = r3_;
            }
#pragma unroll
            for (int i2 = 0; i2 < 4; i2++)
#pragma unroll
                for (int j = 0; j < 4; j++)
                    mma_f16(c[i2][j], a[i2][0], a[i2][1], a[i2][2], a[i2][3], b[j][0], b[j][1]);
        }
    }

    // epilogue: divide by rowsum, write fp32
    const int tr = lane >> 2;
    const int tc = (lane & 3) * 2;
#pragma unroll
    for (int i = 0; i < 4; i++) {
        const size_t row = (size_t)(rm0 + wm * 64 + i * 16 + tr);
        const float d0 = __frcp_rn(divrow[row]);
        const float d1 = __frcp_rn(divrow[row + 8]);
#pragma unroll
        for (int j = 0; j < 4; j++) {
            int col = cn0 + wn * 32 + j * 8 + tc;
            *(float2*)&C[row * ldC + col]       = make_float2(c[i][j][0] * d0, c[i][j][1] * d0);
            *(float2*)&C[(row + 8) * ldC + col] = make_float2(c[i][j][2] * d1, c[i][j][3] * d1);
        }
    }
}

// ---------------- rowsum: warp per row, 4 loads + shfl reduce ----------------
__global__ void rowsum_kernel(const float* __restrict__ part, float* __restrict__ rs) {
    const int warp = (blockIdx.x * blockDim.x + threadIdx.x) >> 5;
    const int lane = threadIdx.x & 31;
    if (warp >= NSEQ) return;
    const float4 v = ((const float4*)(part + (size_t)warp * 128))[lane];
    float s = v.x + v.y + v.z + v.w;
#pragma unroll
    for (int o = 16; o; o >>= 1) s += __shfl_xor_sync(0xffffffffu, s, o);
    if (lane == 0) rs[warp] = s;
}

// ---------------- transpose: Vt[c][r] = fp16(QKV[r][2048 + c]) ----------------
__global__ void transpose_v_kernel(const float* __restrict__ qkv, __half* __restrict__ out) {
    __shared__ float tile[32][33];
    int cbase = blockIdx.x * 32;   // headdim index
    int rbase = blockIdx.y * 32;   // seq index
    int tx = threadIdx.x, ty = threadIdx.y;
#pragma unroll
    for (int j = 0; j < 32; j += 8)
        tile[ty + j][tx] = qkv[(size_t)(rbase + ty + j) * (3 * DIM) + 2 * DIM + cbase + tx];
    __syncthreads();
#pragma unroll
    for (int j = 0; j < 32; j += 8)
        out[(size_t)(cbase + ty + j) * NSEQ + rbase + tx] = __float2half_rn(tile[tx][ty + j]);
}

// ---------------- launch ----------------
extern "C" void kernel_launch(void* const* d_in, const int* in_sizes, int n_in,
                              void* d_out, int out_size) {
    const float* x  = (const float*)d_in[0];
    const float* wq = (const float*)d_in[1];
    const float* wk = (const float*)d_in[2];
    const float* wv = (const float*)d_in[3];
    float* out = (float*)d_out;

    float *p_xt, *p_wt, *p_qkv, *p_part, *p_rs;
    __half *p_vt, *p_S;
    cudaGetSymbolAddress((void**)&p_xt, g_xt);
    cudaGetSymbolAddress((void**)&p_wt, g_wt);
    cudaGetSymbolAddress((void**)&p_qkv, g_qkv);
    cudaGetSymbolAddress((void**)&p_vt, g_vt);
    cudaGetSymbolAddress((void**)&p_S, g_S);
    cudaGetSymbolAddress((void**)&p_part, g_part);
    cudaGetSymbolAddress((void**)&p_rs, g_rowsum);

    cudaFuncSetAttribute(gemm_tt, cudaFuncAttributeMaxDynamicSharedMemorySize, DYN_SMEM_BYTES);
    cudaFuncSetAttribute(gemm_pv, cudaFuncAttributeMaxDynamicSharedMemorySize, DYN_SMEM_BYTES);

    // 1) round inputs to tf32
    convert_kernel<<<2048, 256>>>(x, wq, wk, wv);

    // 2) QKV = xt @ Wt^T (stacked weights), packed [4096, 3072], tf32-rounded out
    gemm_tt<<<dim3(3 * DIM / BN, NSEQ / BM), 256, DYN_SMEM_BYTES>>>(
        p_xt, DIM, p_wt, DIM, p_qkv, nullptr, 3 * DIM, DIM, 1, 0, nullptr);

    // 3) V^T (fp16)
    transpose_v_kernel<<<dim3(DIM / 32, NSEQ / 32), dim3(32, 8)>>>(p_qkv, p_vt);

    // 4) expS = fp16(exp((Q @ K^T)/32)) + row partial sums
    gemm_tt<<<dim3(NSEQ / BN, NSEQ / BM), 256, DYN_SMEM_BYTES>>>(
        p_qkv, 3 * DIM, p_qkv + DIM, 3 * DIM, nullptr, p_S, NSEQ, DIM, 0, 1, p_part);

    // 5) rowsum
    rowsum_kernel<<<NSEQ * 32 / 256, 256>>>(p_part, p_rs);

    // 6) out = (expS @ V) / rowsum   [fp16 mma, 2x rate]
    gemm_pv<<<dim3(DIM / BN, NSEQ / BM), 256, DYN_SMEM_BYTES>>>(
        p_S, NSEQ, p_vt, NSEQ, out, DIM, NSEQ, p_rs);
}